// round 1
// baseline (speedup 1.0000x reference)
#include <cuda_runtime.h>
#include <math.h>

#define N_NODES 50000
#define N_EDGES 800000
#define IN_FEAT 512
#define OUT_FEAT 128

// Scratch: intermediate x = feat @ W, and CSR row pointers (rows are sorted).
__device__ float g_x[(size_t)N_NODES * OUT_FEAT];
__device__ int   g_row_ptr[N_NODES + 1];

// ---------------------------------------------------------------------------
// Kernel 1: row_ptr[i] = lower_bound(rows, i)  (rows sorted ascending)
// ---------------------------------------------------------------------------
__global__ void row_ptr_kernel(const int* __restrict__ rows) {
    int i = blockIdx.x * blockDim.x + threadIdx.x;
    if (i > N_NODES) return;
    int lo = 0, hi = N_EDGES;
    while (lo < hi) {
        int mid = (lo + hi) >> 1;
        if (__ldg(&rows[mid]) < i) lo = mid + 1; else hi = mid;
    }
    g_row_ptr[i] = lo;
}

// ---------------------------------------------------------------------------
// Kernel 2: SGEMM  g_x[M,128] = feat[M,512] @ W[512,128], fp32.
// 128x128 block tile, BK=16, 256 threads, 8x8 register microtile.
// ---------------------------------------------------------------------------
#define BM 128
#define BN 128
#define BK 16
#define TM 8
#define TN 8
#define APAD 4   // pad As row stride to break store bank conflicts

__global__ __launch_bounds__(256, 2) void gemm_kernel(
    const float* __restrict__ A,   // feat [N_NODES, IN_FEAT]
    const float* __restrict__ B)   // weight [IN_FEAT, OUT_FEAT]
{
    __shared__ float As[BK][BM + APAD];  // transposed A tile: As[k][m]
    __shared__ float Bs[BK][BN];         // Bs[k][n]

    const int tid = threadIdx.x;
    const int m0  = blockIdx.x * BM;

    const int tx = tid & 15;   // 0..15  -> n microtile
    const int ty = tid >> 4;   // 0..15  -> m microtile

    // A tile load mapping: 128 rows x 16 cols = 512 float4; 2 per thread.
    const int aRow  = tid >> 2;        // 0..63 (and +64)
    const int aCol4 = (tid & 3) * 4;   // k offset within tile (float4)
    // B tile load mapping: 16 rows x 128 cols = 512 float4; 2 per thread.
    const int bRow  = tid >> 5;        // 0..7 (and +8)
    const int bCol  = (tid & 31) * 4;  // n offset (float4)

    float acc[TM][TN];
    #pragma unroll
    for (int i = 0; i < TM; i++)
        #pragma unroll
        for (int j = 0; j < TN; j++) acc[i][j] = 0.0f;

    for (int k0 = 0; k0 < IN_FEAT; k0 += BK) {
        // Load A tile (guard M edge), store transposed.
        #pragma unroll
        for (int r = 0; r < 2; r++) {
            const int row = aRow + r * 64;
            const int gm  = m0 + row;
            float4 v = make_float4(0.f, 0.f, 0.f, 0.f);
            if (gm < N_NODES)
                v = *(const float4*)&A[(size_t)gm * IN_FEAT + k0 + aCol4];
            As[aCol4 + 0][row] = v.x;
            As[aCol4 + 1][row] = v.y;
            As[aCol4 + 2][row] = v.z;
            As[aCol4 + 3][row] = v.w;
        }
        // Load B tile (always in-bounds: K=512, N=128 exact).
        #pragma unroll
        for (int r = 0; r < 2; r++) {
            const int row = bRow + r * 8;
            *(float4*)&Bs[row][bCol] =
                *(const float4*)&B[(size_t)(k0 + row) * OUT_FEAT + bCol];
        }
        __syncthreads();

        #pragma unroll
        for (int k = 0; k < BK; k++) {
            float rm[TM], rn[TN];
            // vectorized shared loads (2x float4 each) — conflict-free phases
            *(float4*)&rm[0] = *(const float4*)&As[k][ty * TM + 0];
            *(float4*)&rm[4] = *(const float4*)&As[k][ty * TM + 4];
            *(float4*)&rn[0] = *(const float4*)&Bs[k][tx * TN + 0];
            *(float4*)&rn[4] = *(const float4*)&Bs[k][tx * TN + 4];
            #pragma unroll
            for (int i = 0; i < TM; i++)
                #pragma unroll
                for (int j = 0; j < TN; j++)
                    acc[i][j] = fmaf(rm[i], rn[j], acc[i][j]);
        }
        __syncthreads();
    }

    // Write x tile.
    #pragma unroll
    for (int i = 0; i < TM; i++) {
        const int gm = m0 + ty * TM + i;
        if (gm < N_NODES) {
            #pragma unroll
            for (int j = 0; j < TN; j += 4) {
                float4 v = make_float4(acc[i][j], acc[i][j+1], acc[i][j+2], acc[i][j+3]);
                *(float4*)&g_x[(size_t)gm * OUT_FEAT + tx * TN + j] = v;
            }
        }
    }
}

// ---------------------------------------------------------------------------
// Kernel 3: SpMM (warp per row, no atomics) + multispike epilogue.
// out[r] = multispike( sum_{e in [row_ptr[r], row_ptr[r+1])} ew[e] * x[cols[e]] )
// ---------------------------------------------------------------------------
__device__ __forceinline__ float multispike(float x) {
    return floorf(fminf(fmaxf(4.0f * x, 0.0f), 4.0f) + 0.5f) * 0.25f;
}

__global__ __launch_bounds__(256) void spmm_kernel(
    const int*   __restrict__ cols,
    const float* __restrict__ ew,
    float*       __restrict__ out)
{
    const int warp = (blockIdx.x * blockDim.x + threadIdx.x) >> 5;
    const int lane = threadIdx.x & 31;
    if (warp >= N_NODES) return;

    const int e0 = g_row_ptr[warp];
    const int e1 = g_row_ptr[warp + 1];

    float4 acc = make_float4(0.f, 0.f, 0.f, 0.f);
    const int fo = lane * 4;   // this lane's 4 features

    int e = e0;
    // 2x unrolled main loop for memory-level parallelism
    for (; e + 1 < e1; e += 2) {
        const int   c0 = __ldg(&cols[e]);
        const int   c1 = __ldg(&cols[e + 1]);
        const float w0 = __ldg(&ew[e]);
        const float w1 = __ldg(&ew[e + 1]);
        const float4 v0 = *(const float4*)&g_x[(size_t)c0 * OUT_FEAT + fo];
        const float4 v1 = *(const float4*)&g_x[(size_t)c1 * OUT_FEAT + fo];
        acc.x = fmaf(w0, v0.x, acc.x); acc.y = fmaf(w0, v0.y, acc.y);
        acc.z = fmaf(w0, v0.z, acc.z); acc.w = fmaf(w0, v0.w, acc.w);
        acc.x = fmaf(w1, v1.x, acc.x); acc.y = fmaf(w1, v1.y, acc.y);
        acc.z = fmaf(w1, v1.z, acc.z); acc.w = fmaf(w1, v1.w, acc.w);
    }
    if (e < e1) {
        const int   c0 = __ldg(&cols[e]);
        const float w0 = __ldg(&ew[e]);
        const float4 v0 = *(const float4*)&g_x[(size_t)c0 * OUT_FEAT + fo];
        acc.x = fmaf(w0, v0.x, acc.x); acc.y = fmaf(w0, v0.y, acc.y);
        acc.z = fmaf(w0, v0.z, acc.z); acc.w = fmaf(w0, v0.w, acc.w);
    }

    acc.x = multispike(acc.x);
    acc.y = multispike(acc.y);
    acc.z = multispike(acc.z);
    acc.w = multispike(acc.w);
    *(float4*)&out[(size_t)warp * OUT_FEAT + fo] = acc;
}

// ---------------------------------------------------------------------------
extern "C" void kernel_launch(void* const* d_in, const int* in_sizes, int n_in,
                              void* d_out, int out_size) {
    const float* feat   = (const float*)d_in[0];
    const float* weight = (const float*)d_in[1];
    const int*   rows   = (const int*)d_in[2];
    const int*   cols   = (const int*)d_in[3];
    const float* ew     = (const float*)d_in[4];
    float* out = (float*)d_out;

    row_ptr_kernel<<<(N_NODES + 1 + 255) / 256, 256>>>(rows);
    gemm_kernel<<<(N_NODES + BM - 1) / BM, 256>>>(feat, weight);
    spmm_kernel<<<(N_NODES * 32 + 255) / 256, 256>>>(cols, ew, out);
}

// round 3
// speedup vs baseline: 1.4352x; 1.4352x over previous
#include <cuda_runtime.h>
#include <cstdint>
#include <math.h>

#define N_NODES 50000
#define N_EDGES 800000
#define IN_FEAT 512
#define OUT_FEAT 128

// Scratch: intermediate x = feat @ W, and CSR row pointers (rows are sorted).
__device__ float g_x[(size_t)N_NODES * OUT_FEAT];
__device__ int   g_row_ptr[N_NODES + 1];

// ---------------------------------------------------------------------------
// Kernel 1: CSR row pointers via edge-boundary scatter (rows sorted ascending).
// row_ptr[i] = first e with rows[e] >= i.
// ---------------------------------------------------------------------------
__global__ void row_ptr_kernel(const int* __restrict__ rows) {
    int e = blockIdx.x * blockDim.x + threadIdx.x;
    if (e > N_EDGES) return;
    int r1 = (e < N_EDGES) ? __ldg(&rows[e]) : N_NODES;
    int r0 = (e == 0) ? -1 : __ldg(&rows[e - 1]);
    for (int r = r0 + 1; r <= r1; ++r) g_row_ptr[r] = e;
}

// ---------------------------------------------------------------------------
// Kernel 2: 3xTF32 GEMM via warp-level mma.sync (arch-portable PTX).
//   g_x[M,128] = feat[M,512] @ W[512,128]
// CTA tile 128(M) x 128(N); 8 warps in 4(m) x 2(n); warp tile 32 x 64.
// K chunks of 32 staged in dynamic SMEM as hi/lo TF32 splits.
// hi = fp32 with low 13 mantissa bits zeroed (exact in tf32); lo = x - hi.
// Accumulate hi*hi + hi*lo + lo*hi in fp32 => ~2^-21 relative error.
// ---------------------------------------------------------------------------
#define BM 128
#define KC 32
#define NCHUNK (IN_FEAT / KC)     // 16
#define A_STRIDE 36               // floats per A smem row (32 + 4 pad)
#define B_STRIDE 136              // floats per B smem row (128 + 8 pad)
#define SM_AH 0
#define SM_AL (BM * A_STRIDE)                 // 4608
#define SM_BH (2 * BM * A_STRIDE)             // 9216
#define SM_BL (2 * BM * A_STRIDE + KC * B_STRIDE)   // 13568
#define SM_FLOATS (2 * BM * A_STRIDE + 2 * KC * B_STRIDE)  // 17920
#define GEMM_SMEM (SM_FLOATS * 4)             // 71680 bytes

__device__ __forceinline__ float tf32_hi(float x) {
    return __uint_as_float(__float_as_uint(x) & 0xFFFFE000u);
}

#define MMA_TF32(cc, aa, b0, b1)                                               \
    asm volatile(                                                              \
        "mma.sync.aligned.m16n8k8.row.col.f32.tf32.tf32.f32 "                  \
        "{%0,%1,%2,%3}, {%4,%5,%6,%7}, {%8,%9}, {%0,%1,%2,%3};"                \
        : "+f"((cc)[0]), "+f"((cc)[1]), "+f"((cc)[2]), "+f"((cc)[3])           \
        : "r"((aa)[0]), "r"((aa)[1]), "r"((aa)[2]), "r"((aa)[3]),              \
          "r"(b0), "r"(b1))

__global__ __launch_bounds__(256, 2) void gemm_mma_kernel(
    const float* __restrict__ A,   // feat [N_NODES, 512]
    const float* __restrict__ B)   // weight [512, 128]
{
    extern __shared__ float sm[];
    float* sAh = sm + SM_AH;
    float* sAl = sm + SM_AL;
    float* sBh = sm + SM_BH;
    float* sBl = sm + SM_BL;

    const int tid  = threadIdx.x;
    const int wid  = tid >> 5;
    const int lane = tid & 31;
    const int g    = lane >> 2;    // groupID 0..7
    const int t4   = lane & 3;     // 0..3
    const int wm   = wid & 3;      // warp m index (0..3)
    const int wn   = wid >> 2;     // warp n index (0..1)
    const int m0   = blockIdx.x * BM;

    float c[2][8][4];
    #pragma unroll
    for (int i = 0; i < 2; i++)
        #pragma unroll
        for (int j = 0; j < 8; j++)
            #pragma unroll
            for (int q = 0; q < 4; q++) c[i][j][q] = 0.0f;

    for (int ch = 0; ch < NCHUNK; ++ch) {
        const int k0 = ch * KC;

        // ---- fill A: 128 m-rows x 8 float4 (k) ----
        #pragma unroll
        for (int it = 0; it < 4; ++it) {
            const int slot = it * 256 + tid;     // 0..1023
            const int m  = slot >> 3;
            const int k4 = slot & 7;
            const int gm = m0 + m;
            float4 v = make_float4(0.f, 0.f, 0.f, 0.f);
            if (gm < N_NODES)
                v = *(const float4*)&A[(size_t)gm * IN_FEAT + k0 + k4 * 4];
            float4 h, l;
            h.x = tf32_hi(v.x); l.x = v.x - h.x;
            h.y = tf32_hi(v.y); l.y = v.y - h.y;
            h.z = tf32_hi(v.z); l.z = v.z - h.z;
            h.w = tf32_hi(v.w); l.w = v.w - h.w;
            *(float4*)&sAh[m * A_STRIDE + k4 * 4] = h;
            *(float4*)&sAl[m * A_STRIDE + k4 * 4] = l;
        }
        // ---- fill B: 32 k-rows x 32 float4 (n) ----
        #pragma unroll
        for (int it = 0; it < 4; ++it) {
            const int slot = it * 256 + tid;     // 0..1023
            const int k  = slot >> 5;
            const int n4 = slot & 31;
            float4 v = *(const float4*)&B[(size_t)(k0 + k) * OUT_FEAT + n4 * 4];
            float4 h, l;
            h.x = tf32_hi(v.x); l.x = v.x - h.x;
            h.y = tf32_hi(v.y); l.y = v.y - h.y;
            h.z = tf32_hi(v.z); l.z = v.z - h.z;
            h.w = tf32_hi(v.w); l.w = v.w - h.w;
            *(float4*)&sBh[k * B_STRIDE + n4 * 4] = h;
            *(float4*)&sBl[k * B_STRIDE + n4 * 4] = l;
        }
        __syncthreads();

        // ---- compute: 4 k8-steps ----
        #pragma unroll
        for (int ks = 0; ks < 4; ++ks) {
            const int kb = ks * 8;
            uint32_t ah[2][4], al[2][4];
            #pragma unroll
            for (int mb = 0; mb < 2; ++mb) {
                const int r0 = wm * 32 + mb * 16 + g;
                const int base0 = r0 * A_STRIDE + kb + t4;
                const int base1 = (r0 + 8) * A_STRIDE + kb + t4;
                ah[mb][0] = __float_as_uint(sAh[base0]);
                ah[mb][1] = __float_as_uint(sAh[base1]);
                ah[mb][2] = __float_as_uint(sAh[base0 + 4]);
                ah[mb][3] = __float_as_uint(sAh[base1 + 4]);
                al[mb][0] = __float_as_uint(sAl[base0]);
                al[mb][1] = __float_as_uint(sAl[base1]);
                al[mb][2] = __float_as_uint(sAl[base0 + 4]);
                al[mb][3] = __float_as_uint(sAl[base1 + 4]);
            }
            #pragma unroll
            for (int nb = 0; nb < 8; ++nb) {
                const int nc = wn * 64 + nb * 8 + g;
                const uint32_t bh0 = __float_as_uint(sBh[(kb + t4) * B_STRIDE + nc]);
                const uint32_t bh1 = __float_as_uint(sBh[(kb + t4 + 4) * B_STRIDE + nc]);
                const uint32_t bl0 = __float_as_uint(sBl[(kb + t4) * B_STRIDE + nc]);
                const uint32_t bl1 = __float_as_uint(sBl[(kb + t4 + 4) * B_STRIDE + nc]);
                #pragma unroll
                for (int mb = 0; mb < 2; ++mb) {
                    MMA_TF32(c[mb][nb], ah[mb], bh0, bh1);   // hi*hi
                    MMA_TF32(c[mb][nb], ah[mb], bl0, bl1);   // hi*lo
                    MMA_TF32(c[mb][nb], al[mb], bh0, bh1);   // lo*hi
                }
            }
        }
        __syncthreads();
    }

    // ---- epilogue: write c fragments to g_x ----
    #pragma unroll
    for (int mb = 0; mb < 2; ++mb) {
        #pragma unroll
        for (int half = 0; half < 2; ++half) {
            const int row = m0 + wm * 32 + mb * 16 + g + half * 8;
            if (row < N_NODES) {
                #pragma unroll
                for (int nb = 0; nb < 8; ++nb) {
                    const int col = wn * 64 + nb * 8 + 2 * t4;
                    float2 v = make_float2(c[mb][nb][2 * half],
                                           c[mb][nb][2 * half + 1]);
                    *(float2*)&g_x[(size_t)row * OUT_FEAT + col] = v;
                }
            }
        }
    }
}

// ---------------------------------------------------------------------------
// Kernel 3: SpMM (warp per row, no atomics) + multispike epilogue.
// ---------------------------------------------------------------------------
__device__ __forceinline__ float multispike(float x) {
    return floorf(fminf(fmaxf(4.0f * x, 0.0f), 4.0f) + 0.5f) * 0.25f;
}

__global__ __launch_bounds__(256) void spmm_kernel(
    const int*   __restrict__ cols,
    const float* __restrict__ ew,
    float*       __restrict__ out)
{
    const int warp = (blockIdx.x * blockDim.x + threadIdx.x) >> 5;
    const int lane = threadIdx.x & 31;
    if (warp >= N_NODES) return;

    const int e0 = g_row_ptr[warp];
    const int e1 = g_row_ptr[warp + 1];

    float4 acc = make_float4(0.f, 0.f, 0.f, 0.f);
    const int fo = lane * 4;

    int e = e0;
    for (; e + 1 < e1; e += 2) {
        const int   c0 = __ldg(&cols[e]);
        const int   c1 = __ldg(&cols[e + 1]);
        const float w0 = __ldg(&ew[e]);
        const float w1 = __ldg(&ew[e + 1]);
        const float4 v0 = *(const float4*)&g_x[(size_t)c0 * OUT_FEAT + fo];
        const float4 v1 = *(const float4*)&g_x[(size_t)c1 * OUT_FEAT + fo];
        acc.x = fmaf(w0, v0.x, acc.x); acc.y = fmaf(w0, v0.y, acc.y);
        acc.z = fmaf(w0, v0.z, acc.z); acc.w = fmaf(w0, v0.w, acc.w);
        acc.x = fmaf(w1, v1.x, acc.x); acc.y = fmaf(w1, v1.y, acc.y);
        acc.z = fmaf(w1, v1.z, acc.z); acc.w = fmaf(w1, v1.w, acc.w);
    }
    if (e < e1) {
        const int   c0 = __ldg(&cols[e]);
        const float w0 = __ldg(&ew[e]);
        const float4 v0 = *(const float4*)&g_x[(size_t)c0 * OUT_FEAT + fo];
        acc.x = fmaf(w0, v0.x, acc.x); acc.y = fmaf(w0, v0.y, acc.y);
        acc.z = fmaf(w0, v0.z, acc.z); acc.w = fmaf(w0, v0.w, acc.w);
    }

    acc.x = multispike(acc.x);
    acc.y = multispike(acc.y);
    acc.z = multispike(acc.z);
    acc.w = multispike(acc.w);
    *(float4*)&out[(size_t)warp * OUT_FEAT + fo] = acc;
}

// ---------------------------------------------------------------------------
extern "C" void kernel_launch(void* const* d_in, const int* in_sizes, int n_in,
                              void* d_out, int out_size) {
    const float* feat   = (const float*)d_in[0];
    const float* weight = (const float*)d_in[1];
    const int*   rows   = (const int*)d_in[2];
    const int*   cols   = (const int*)d_in[3];
    const float* ew     = (const float*)d_in[4];
    float* out = (float*)d_out;

    static int configured = 0;
    if (!configured) {
        cudaFuncSetAttribute(gemm_mma_kernel,
                             cudaFuncAttributeMaxDynamicSharedMemorySize,
                             GEMM_SMEM);
        configured = 1;
    }

    row_ptr_kernel<<<(N_EDGES + 1 + 255) / 256, 256>>>(rows);
    gemm_mma_kernel<<<(N_NODES + BM - 1) / BM, 256, GEMM_SMEM>>>(feat, weight);
    spmm_kernel<<<(N_NODES * 32 + 255) / 256, 256>>>(cols, ew, out);
}